// round 3
// baseline (speedup 1.0000x reference)
#include <cuda_runtime.h>
#include <math.h>

#ifndef M_PI
#define M_PI 3.14159265358979323846
#endif

#define BB   4
#define HH   64
#define WW   64
#define LL   4096     // HH*WW
#define DM   96
#define DI   192      // 2*DM
#define KK   4
#define DS   16
#define DTR  6
#define CDT  38       // DTR + 2*DS
#define C2   384      // 2*DI

// ---------------- device scratch (static, no allocation) ----------------
__device__ int    g_idx[KK][LL];
__device__ int    g_inv[KK][LL];
__device__ double g_key3[LL];
__device__ double g_key4[LL];
__device__ float  g_wpf[LL][KK];
__device__ float  g_xz[BB * LL * C2];        // 25 MB
__device__ float  g_xconv[BB * LL * DI];     // 12.6 MB, layout (b, pos, d)
__device__ float  g_dts[BB * KK * LL * DI];  // 50 MB, stores DELTA (post-softplus), (bk, l, d)
__device__ float  g_Bs[BB * KK * LL * DS];   // (bk, l, n)
__device__ float  g_Cs[BB * KK * LL * DS];
__device__ float  g_ys[BB * KK * LL * DI];   // 50 MB, layout (bk, l, d)

// ---------------- kernel 1: scan orders, radial keys, position-fusion weights --
__global__ void k_orders(const float* __restrict__ pf_w1, const float* __restrict__ pf_b1,
                         const float* __restrict__ pf_w2, const float* __restrict__ pf_b2) {
    int p = blockIdx.x * blockDim.x + threadIdx.x;
    if (p >= LL) return;
    int i = p / WW, j = p % WW;

    // o1: diagonal snake (s = i+j)
    {
        int s = i + j;
        int len = (s < WW) ? (s + 1) : (2 * WW - 1 - s);
        int off = (s < WW) ? (s * (s + 1) / 2)
                           : (2080 + 2016 - (127 - s) * (128 - s) / 2);
        int pos = i - max(0, s - (WW - 1));
        if (s & 1) pos = len - 1 - pos;
        g_idx[0][off + pos] = p;
    }
    // o2: anti-diagonal snake (s = i + (W-1-j))
    {
        int s = i + (WW - 1 - j);
        int len = (s < WW) ? (s + 1) : (2 * WW - 1 - s);
        int off = (s < WW) ? (s * (s + 1) / 2)
                           : (2080 + 2016 - (127 - s) * (128 - s) / 2);
        int pos = i - max(0, s - (WW - 1));
        if (s & 1) pos = len - 1 - pos;
        g_idx[1][off + pos] = p;
    }
    // radial keys (float64, to match numpy argsort ordering)
    {
        int dyi = i - HH / 2, dxi = j - WW / 2;
        double r = sqrt((double)(dyi * dyi + dxi * dxi));
        double th = atan2((double)dyi, (double)dxi);
        g_key3[p] =  r * (double)(LL + 1) + (th + M_PI) * 10.0;
        g_key4[p] = -r * (double)(LL + 1) + (th + M_PI) * 10.0;
    }
    // position-fusion MLP weights (float32, matches jnp path)
    {
        float dy = ((float)i - (float)HH * 0.5f) / ((float)HH * 0.5f);
        float dx = ((float)j - (float)WW * 0.5f) / ((float)WW * 0.5f);
        float rf = sqrtf(dy * dy + dx * dx);
        rf = fminf(rf, 2.0f);
        float tf = atan2f(dy, dx) / (float)M_PI;
        float logits[KK];
#pragma unroll
        for (int k = 0; k < KK; k++) logits[k] = pf_b2[k];
        for (int h = 0; h < 32; h++) {
            float a = rf * pf_w1[h * 2 + 0] + tf * pf_w1[h * 2 + 1] + pf_b1[h];
            float ge = 0.5f * a * (1.0f + erff(a * 0.70710678118654752f));
#pragma unroll
            for (int k = 0; k < KK; k++) logits[k] += ge * pf_w2[k * 32 + h];
        }
        float m = logits[0];
#pragma unroll
        for (int k = 1; k < KK; k++) m = fmaxf(m, logits[k]);
        float s = 0.f, e[KK];
#pragma unroll
        for (int k = 0; k < KK; k++) { e[k] = expf(logits[k] - m); s += e[k]; }
        float inv = 1.0f / s;
#pragma unroll
        for (int k = 0; k < KK; k++) g_wpf[p][k] = e[k] * inv;
    }
}

// ---------------- kernel 2: rank (argsort) of radial keys ----------------
__global__ void k_rank() {
    __shared__ double sk[LL];   // 32 KB
    int which = blockIdx.y;     // 0 -> key3, 1 -> key4
    const double* keys = which ? g_key4 : g_key3;
    for (int t = threadIdx.x; t < LL; t += blockDim.x) sk[t] = keys[t];
    __syncthreads();
    int i = blockIdx.x * blockDim.x + threadIdx.x;
    if (i >= LL) return;
    double ki = sk[i];
    int cnt = 0;
    for (int j = 0; j < LL; j++) {
        double kj = sk[j];
        cnt += (kj < ki) || (kj == ki && j < i);
    }
    g_idx[2 + which][cnt] = i;
}

// ---------------- kernel 3: inverse permutations ----------------
__global__ void k_invperm() {
    int t = blockIdx.x * blockDim.x + threadIdx.x;
    if (t >= KK * LL) return;
    int k = t / LL, l = t % LL;
    g_inv[k][g_idx[k][l]] = l;
}

// ---------------- kernel 4: in-projection GEMM ----------------
// xz[row, c] = sum_j x[row, j] * W[c, j],  row in [0, B*L), c in [0, 384)
__global__ void k_inproj(const float* __restrict__ x, const float* __restrict__ w) {
    __shared__ float4 xr[DM / 4];
    int row = blockIdx.x;
    int c = threadIdx.x;
    if (threadIdx.x < DM / 4)
        xr[threadIdx.x] = ((const float4*)(x + (size_t)row * DM))[threadIdx.x];
    __syncthreads();
    const float4* wr = (const float4*)(w + (size_t)c * DM);
    float acc = 0.f;
#pragma unroll
    for (int q = 0; q < DM / 4; q++) {
        float4 wv = __ldg(&wr[q]);
        float4 xv = xr[q];
        acc += wv.x * xv.x + wv.y * xv.y + wv.z * xv.z + wv.w * xv.w;
    }
    g_xz[(size_t)row * C2 + c] = acc;
}

// ---------------- kernel 5: depthwise 3x3 conv + bias + SiLU ----------------
__global__ void k_conv(const float* __restrict__ cw, const float* __restrict__ cb) {
    int bp = blockIdx.x;              // b*L + p
    int d = threadIdx.x;              // 192
    int b = bp >> 12, p = bp & (LL - 1);
    int i = p >> 6, j = p & 63;
    float acc = cb[d];
#pragma unroll
    for (int ky = 0; ky < 3; ky++) {
        int y = i + ky - 1;
        if ((unsigned)y < HH) {
#pragma unroll
            for (int kx = 0; kx < 3; kx++) {
                int xx = j + kx - 1;
                if ((unsigned)xx < WW) {
                    acc += g_xz[(size_t)(((b << 12) + (y << 6) + xx)) * C2 + d]
                         * cw[d * 9 + ky * 3 + kx];
                }
            }
        }
    }
    float sv = acc / (1.0f + expf(-acc));
    g_xconv[(size_t)bp * DI + d] = sv;
}

// ---------------- kernel 6: x_dbl projection + dt/B/C (+ softplus fused) ------
#define LT 32
__global__ void k_xproj(const float* __restrict__ xpw, const float* __restrict__ dtw,
                        const float* __restrict__ dirB, const float* __restrict__ dt_bias) {
    __shared__ float xs[LT][DI + 1];        // pad 193: conflict-free column reads
    __shared__ float xdbl[LT][CDT + 3];     // pad 41: conflict-free writes
    int bk = blockIdx.x;                    // 16
    int b = bk >> 2, k = bk & 3;
    int l0 = blockIdx.y * LT;
    int tid = threadIdx.x;                  // 256

    for (int t = tid; t < LT * DI; t += 256) {
        int li = t / DI, d = t % DI;
        int pos = g_idx[k][l0 + li];
        xs[li][d] = g_xconv[(size_t)((b << 12) + pos) * DI + d];
    }
    __syncthreads();

    for (int t = tid; t < CDT * LT; t += 256) {
        int c = t >> 5, li = t & (LT - 1);
        const float* wrow = xpw + (size_t)(k * CDT + c) * DI;
        float acc = 0.f;
#pragma unroll 8
        for (int d = 0; d < DI; d++) acc += xs[li][d] * __ldg(&wrow[d]);
        xdbl[li][c] = acc;
    }
    __syncthreads();

    for (int t = tid; t < LT * DI; t += 256) {
        int li = t / DI, d = t % DI;
        const float* wd = dtw + (size_t)(k * DI + d) * DTR;
        float acc = 0.f;
#pragma unroll
        for (int r = 0; r < DTR; r++) acc += xdbl[li][r] * __ldg(&wd[r]);
        // fused: delta = softplus(dt + bias), precomputed here (float32, matches ref)
        float xsp = acc + __ldg(&dt_bias[k * DI + d]);
        float delta = (xsp > 0.f) ? (xsp + __logf(1.0f + __expf(-xsp)))
                                  : __logf(1.0f + __expf(xsp));
        g_dts[((size_t)(bk << 12) + l0 + li) * DI + d] = delta;
    }
    for (int t = tid; t < LT * DS; t += 256) {
        int li = t >> 4, n = t & 15;
        g_Bs[((size_t)(bk << 12) + l0 + li) * DS + n] = xdbl[li][DTR + n] + dirB[k * DS + n];
        g_Cs[((size_t)(bk << 12) + l0 + li) * DS + n] = xdbl[li][DTR + DS + n];
    }
}

// ---------------- kernel 7: selective scan (4 threads per channel, 4 states each) --
// grid: 96 = (b,k) x 6 chunks of 32 channels; block: 128 threads
__global__ void k_scan(const float* __restrict__ A_logs, const float* __restrict__ Ds_) {
    int blk = blockIdx.x;
    int bk = blk / 6, chunk = blk % 6;
    int b = bk >> 2, k = bk & 3;
    int t = threadIdx.x;
    int ch = t >> 2;                 // 0..31
    int q = t & 3;                   // state quad: n in [4q, 4q+4)
    int d = chunk * 32 + ch;
    int row = k * DI + d;

    float A[4];
    bool powmode = true;
#pragma unroll
    for (int j = 0; j < 4; j++) {
        int n = 4 * q + j;
        A[j] = -expf(A_logs[(size_t)row * DS + n]);
        if (fabsf(A[j] + (float)(n + 1)) > 1e-3f) powmode = false;
    }
    float Dv = Ds_[row];
    float h0 = 0.f, h1 = 0.f, h2 = 0.f, h3 = 0.f;

    const float* dts_base = g_dts + ((size_t)bk << 12) * DI;   // holds delta
    const float4* Bb = (const float4*)(g_Bs + ((size_t)bk << 12) * DS);
    const float4* Cb = (const float4*)(g_Cs + ((size_t)bk << 12) * DS);
    float* yout = g_ys + ((size_t)bk << 12) * DI;
    const int* idxk = g_idx[k];

    // prefetch l = 0
    float delta = __ldg(&dts_base[d]);
    float u = __ldg(&g_xconv[(size_t)((b << 12) + __ldg(&idxk[0])) * DI + d]);
    float4 Bc = __ldg(&Bb[q]);
    float4 Cc = __ldg(&Cb[q]);

    for (int l = 0; l < LL; l++) {
        // software-pipelined prefetch of step l+1
        float delta_n = 0.f, u_n = 0.f;
        float4 Bn = make_float4(0.f, 0.f, 0.f, 0.f);
        float4 Cn = Bn;
        int ln = l + 1;
        if (ln < LL) {
            int posn = __ldg(&idxk[ln]);
            delta_n = __ldg(&dts_base[(size_t)ln * DI + d]);
            u_n = __ldg(&g_xconv[(size_t)((b << 12) + posn) * DI + d]);
            Bn = __ldg(&Bb[ln * 4 + q]);
            Cn = __ldg(&Cb[ln * 4 + q]);
        }

        // compute step l  (delta already softplus'ed)
        float du = delta * u;
        float e0, e1, e2, e3;
        if (powmode) {
            float pw  = __expf(-delta);      // exp(-delta * 1)
            float pw2 = pw * pw;
            float pw4 = pw2 * pw2;
            float pw8 = pw4 * pw4;
            float pw12 = pw8 * pw4;
            float base = (q == 0) ? 1.0f : (q == 1) ? pw4 : (q == 2) ? pw8 : pw12;
            e0 = base * pw;                  // exp(delta*A[4q+0]),  A_n = -(n+1)
            e1 = base * pw2;
            e2 = e1 * pw;
            e3 = base * pw4;
        } else {
            e0 = __expf(delta * A[0]);
            e1 = __expf(delta * A[1]);
            e2 = __expf(delta * A[2]);
            e3 = __expf(delta * A[3]);
        }
        h0 = fmaf(du, Bc.x, h0 * e0);
        h1 = fmaf(du, Bc.y, h1 * e1);
        h2 = fmaf(du, Bc.z, h2 * e2);
        h3 = fmaf(du, Bc.w, h3 * e3);
        float ya = fmaf(h0, Cc.x, h1 * Cc.y);
        float yb = fmaf(h2, Cc.z, h3 * Cc.w);
        float y = ya + yb;
        // reduce over the 4 state-quads (adjacent lanes)
        y += __shfl_xor_sync(0xFFFFFFFFu, y, 1);
        y += __shfl_xor_sync(0xFFFFFFFFu, y, 2);
        if (q == 0) yout[(size_t)l * DI + d] = y + Dv * u;

        delta = delta_n; u = u_n; Bc = Bn; Cc = Cn;
    }
}

// ---------------- kernel 8: direction fusion + LN + SiLU gate + out-proj ------
__global__ void k_final(const float* __restrict__ ln_g, const float* __restrict__ ln_b,
                        const float* __restrict__ opw, float* __restrict__ out) {
    __shared__ float tbuf[DI];
    __shared__ float w1s[6], w2s[6];
    __shared__ float mrs[2];
    int bp = blockIdx.x;               // b*L + p
    int b = bp >> 12, p = bp & (LL - 1);
    int d = threadIdx.x;               // 192

    float acc = 0.f;
#pragma unroll
    for (int k = 0; k < KK; k++) {
        int l = g_inv[k][p];
        acc += g_ys[((size_t)(((b << 2) + k) << 12) + l) * DI + d] * g_wpf[p][k];
    }

    // block reduce: sum, sumsq
    float s1 = acc, s2 = acc * acc;
#pragma unroll
    for (int o = 16; o; o >>= 1) {
        s1 += __shfl_xor_sync(0xFFFFFFFFu, s1, o);
        s2 += __shfl_xor_sync(0xFFFFFFFFu, s2, o);
    }
    int wid = d >> 5, lid = d & 31;
    if (lid == 0) { w1s[wid] = s1; w2s[wid] = s2; }
    __syncthreads();
    if (d == 0) {
        float t1 = 0.f, t2 = 0.f;
#pragma unroll
        for (int w = 0; w < 6; w++) { t1 += w1s[w]; t2 += w2s[w]; }
        float mean = t1 * (1.0f / DI);
        float var = t2 * (1.0f / DI) - mean * mean;
        mrs[0] = mean;
        mrs[1] = rsqrtf(var + 1e-5f);
    }
    __syncthreads();

    float yn = (acc - mrs[0]) * mrs[1] * ln_g[d] + ln_b[d];
    float z = g_xz[(size_t)((b << 12) + p) * C2 + DI + d];
    float tv = yn * (z / (1.0f + expf(-z)));
    tbuf[d] = tv;
    __syncthreads();

    if (d < DM) {
        const float* wr = opw + (size_t)d * DI;
        float o = 0.f;
#pragma unroll 8
        for (int dd = 0; dd < DI; dd++) o += tbuf[dd] * __ldg(&wr[dd]);
        out[(size_t)bp * DM + d] = o;
    }
}

// ---------------- launch ----------------
extern "C" void kernel_launch(void* const* d_in, const int* in_sizes, int n_in,
                              void* d_out, int out_size) {
    const float* x          = (const float*)d_in[0];
    const float* in_proj_w  = (const float*)d_in[1];
    const float* conv_w     = (const float*)d_in[2];
    const float* conv_b     = (const float*)d_in[3];
    const float* x_proj_w   = (const float*)d_in[4];
    const float* dt_projs_w = (const float*)d_in[5];
    const float* dt_projs_b = (const float*)d_in[6];
    const float* A_logs     = (const float*)d_in[7];
    const float* Ds         = (const float*)d_in[8];
    const float* dir_Bs     = (const float*)d_in[9];
    const float* pf_w1      = (const float*)d_in[10];
    const float* pf_b1      = (const float*)d_in[11];
    const float* pf_w2      = (const float*)d_in[12];
    const float* pf_b2      = (const float*)d_in[13];
    const float* ln_g       = (const float*)d_in[14];
    const float* ln_b       = (const float*)d_in[15];
    const float* out_proj_w = (const float*)d_in[16];
    float* out = (float*)d_out;

    k_orders<<<LL / 256, 256>>>(pf_w1, pf_b1, pf_w2, pf_b2);
    k_rank<<<dim3(LL / 256, 2), 256>>>();
    k_invperm<<<(KK * LL) / 256, 256>>>();
    k_inproj<<<BB * LL, C2>>>(x, in_proj_w);
    k_conv<<<BB * LL, DI>>>(conv_w, conv_b);
    k_xproj<<<dim3(BB * KK, LL / LT), 256>>>(x_proj_w, dt_projs_w, dir_Bs, dt_projs_b);
    k_scan<<<BB * KK * 6, 128>>>(A_logs, Ds);
    k_final<<<BB * LL, DI>>>(ln_g, ln_b, out_proj_w, out);
}

// round 5
// speedup vs baseline: 2.1449x; 2.1449x over previous
#include <cuda_runtime.h>
#include <math.h>

#ifndef M_PI
#define M_PI 3.14159265358979323846
#endif

#define BB   4
#define HH   64
#define WW   64
#define LL   4096     // HH*WW
#define DM   96
#define DI   192      // 2*DM
#define KK   4
#define DS   16
#define DTR  6
#define CDT  38       // DTR + 2*DS
#define C2   384      // 2*DI

// ---------------- device scratch (static, no allocation) ----------------
__device__ int    g_idx[KK][LL];
__device__ int    g_inv[KK][LL];
__device__ unsigned long long g_key3[LL];   // order-preserving uint64 images of fp64 keys
__device__ unsigned long long g_key4[LL];
__device__ float  g_wpf[LL][KK];
__device__ float  g_xz[BB * LL * C2];            // 25 MB
__device__ float  g_xconv[BB * LL * DI];         // 12.6 MB, layout (b, pos, d)
__device__ float4 g_du4[BB * KK * LL * DI / 2];  // 100 MB: (delta,u) float2 pairs, (bk,l,d)
__device__ float  g_Bs[BB * KK * LL * DS];       // (bk, l, n)
__device__ float  g_Cs[BB * KK * LL * DS];
__device__ float  g_ys[BB * KK * LL * DI];       // 50 MB, layout (bk, l, d)

// order-preserving map double -> uint64 (no NaNs here; keys finite)
__device__ __forceinline__ unsigned long long d2u(double v) {
    unsigned long long b = __double_as_longlong(v);
    return (b & 0x8000000000000000ULL) ? ~b : (b | 0x8000000000000000ULL);
}

// ---------------- kernel 1: scan orders, radial keys, position-fusion weights --
__global__ void k_orders(const float* __restrict__ pf_w1, const float* __restrict__ pf_b1,
                         const float* __restrict__ pf_w2, const float* __restrict__ pf_b2) {
    int p = blockIdx.x * blockDim.x + threadIdx.x;
    if (p >= LL) return;
    int i = p / WW, j = p % WW;

    // o1: diagonal snake (s = i+j)
    {
        int s = i + j;
        int len = (s < WW) ? (s + 1) : (2 * WW - 1 - s);
        int off = (s < WW) ? (s * (s + 1) / 2)
                           : (2080 + 2016 - (127 - s) * (128 - s) / 2);
        int pos = i - max(0, s - (WW - 1));
        if (s & 1) pos = len - 1 - pos;
        g_idx[0][off + pos] = p;
    }
    // o2: anti-diagonal snake (s = i + (W-1-j))
    {
        int s = i + (WW - 1 - j);
        int len = (s < WW) ? (s + 1) : (2 * WW - 1 - s);
        int off = (s < WW) ? (s * (s + 1) / 2)
                           : (2080 + 2016 - (127 - s) * (128 - s) / 2);
        int pos = i - max(0, s - (WW - 1));
        if (s & 1) pos = len - 1 - pos;
        g_idx[1][off + pos] = p;
    }
    // radial keys (float64 math to match numpy argsort, then order-preserving uint64)
    {
        int dyi = i - HH / 2, dxi = j - WW / 2;
        double r = sqrt((double)(dyi * dyi + dxi * dxi));
        double th = atan2((double)dyi, (double)dxi);
        g_key3[p] = d2u( r * (double)(LL + 1) + (th + M_PI) * 10.0);
        g_key4[p] = d2u(-r * (double)(LL + 1) + (th + M_PI) * 10.0);
    }
    // position-fusion MLP weights (float32, matches jnp path)
    {
        float dy = ((float)i - (float)HH * 0.5f) / ((float)HH * 0.5f);
        float dx = ((float)j - (float)WW * 0.5f) / ((float)WW * 0.5f);
        float rf = sqrtf(dy * dy + dx * dx);
        rf = fminf(rf, 2.0f);
        float tf = atan2f(dy, dx) / (float)M_PI;
        float logits[KK];
#pragma unroll
        for (int k = 0; k < KK; k++) logits[k] = pf_b2[k];
        for (int h = 0; h < 32; h++) {
            float a = rf * pf_w1[h * 2 + 0] + tf * pf_w1[h * 2 + 1] + pf_b1[h];
            float ge = 0.5f * a * (1.0f + erff(a * 0.70710678118654752f));
#pragma unroll
            for (int k = 0; k < KK; k++) logits[k] += ge * pf_w2[k * 32 + h];
        }
        float m = logits[0];
#pragma unroll
        for (int k = 1; k < KK; k++) m = fmaxf(m, logits[k]);
        float s = 0.f, e[KK];
#pragma unroll
        for (int k = 0; k < KK; k++) { e[k] = expf(logits[k] - m); s += e[k]; }
        float inv = 1.0f / s;
#pragma unroll
        for (int k = 0; k < KK; k++) g_wpf[p][k] = e[k] * inv;
    }
}

// ---------------- kernel 2: rank (argsort) of radial keys, integer compares ----
__global__ void k_rank() {
    __shared__ unsigned long long sk[LL];   // 32 KB
    int which = blockIdx.y;     // 0 -> key3, 1 -> key4
    const unsigned long long* keys = which ? g_key4 : g_key3;
    for (int t = threadIdx.x; t < LL; t += blockDim.x) sk[t] = keys[t];
    __syncthreads();
    int i = blockIdx.x * blockDim.x + threadIdx.x;
    if (i >= LL) return;
    unsigned long long ki = sk[i];
    int cnt = 0;
    for (int j = 0; j < LL; j++) {
        unsigned long long kj = sk[j];
        cnt += (kj < ki) || (kj == ki && j < i);
    }
    g_idx[2 + which][cnt] = i;
}

// ---------------- kernel 3: inverse permutations ----------------
__global__ void k_invperm() {
    int t = blockIdx.x * blockDim.x + threadIdx.x;
    if (t >= KK * LL) return;
    int k = t / LL, l = t % LL;
    g_inv[k][g_idx[k][l]] = l;
}

// ---------------- kernel 4: in-projection GEMM (64x64 smem-tiled) ----------
// C[row, c] = sum_j X[row, j] * W[c, j];  X: 16384x96, W: 384x96, C: 16384x384
#define GM 64
#define GN 64
#define GK 32
__global__ void k_inproj(const float* __restrict__ x, const float* __restrict__ w) {
    __shared__ float As[GM][GK];        // 8 KB
    __shared__ float Bs[GK][GN + 4];    // pad: row stride 68 (float4-aligned, conflict-light)
    int col0 = blockIdx.x * GN;         // 6
    int row0 = blockIdx.y * GM;         // 256
    int t = threadIdx.x;                // 256
    int tx = t & 15, ty = t >> 4;

    float acc[4][4] = {};
#pragma unroll
    for (int k0 = 0; k0 < DM; k0 += GK) {
        // load As: 64 rows x 32 k = 512 float4, 2 per thread
#pragma unroll
        for (int r = 0; r < 2; r++) {
            int idx = t + r * 256;
            int ar = idx >> 3, ac4 = idx & 7;
            float4 v = *(const float4*)(x + (size_t)(row0 + ar) * DM + k0 + ac4 * 4);
            *(float4*)&As[ar][ac4 * 4] = v;
        }
        // load Bs transposed: W[col0+c][k0+k] -> Bs[k][c]
#pragma unroll
        for (int r = 0; r < 2; r++) {
            int idx = t + r * 256;
            int c = idx >> 3, k4 = idx & 7;
            float4 v = *(const float4*)(w + (size_t)(col0 + c) * DM + k0 + k4 * 4);
            Bs[k4 * 4 + 0][c] = v.x;
            Bs[k4 * 4 + 1][c] = v.y;
            Bs[k4 * 4 + 2][c] = v.z;
            Bs[k4 * 4 + 3][c] = v.w;
        }
        __syncthreads();
#pragma unroll
        for (int kk = 0; kk < GK; kk++) {
            float a0 = As[ty * 4 + 0][kk];
            float a1 = As[ty * 4 + 1][kk];
            float a2 = As[ty * 4 + 2][kk];
            float a3 = As[ty * 4 + 3][kk];
            float4 bv = *(const float4*)&Bs[kk][tx * 4];
            acc[0][0] = fmaf(a0, bv.x, acc[0][0]); acc[0][1] = fmaf(a0, bv.y, acc[0][1]);
            acc[0][2] = fmaf(a0, bv.z, acc[0][2]); acc[0][3] = fmaf(a0, bv.w, acc[0][3]);
            acc[1][0] = fmaf(a1, bv.x, acc[1][0]); acc[1][1] = fmaf(a1, bv.y, acc[1][1]);
            acc[1][2] = fmaf(a1, bv.z, acc[1][2]); acc[1][3] = fmaf(a1, bv.w, acc[1][3]);
            acc[2][0] = fmaf(a2, bv.x, acc[2][0]); acc[2][1] = fmaf(a2, bv.y, acc[2][1]);
            acc[2][2] = fmaf(a2, bv.z, acc[2][2]); acc[2][3] = fmaf(a2, bv.w, acc[2][3]);
            acc[3][0] = fmaf(a3, bv.x, acc[3][0]); acc[3][1] = fmaf(a3, bv.y, acc[3][1]);
            acc[3][2] = fmaf(a3, bv.z, acc[3][2]); acc[3][3] = fmaf(a3, bv.w, acc[3][3]);
        }
        __syncthreads();
    }
#pragma unroll
    for (int i = 0; i < 4; i++) {
        int row = row0 + ty * 4 + i;
        float4 v = make_float4(acc[i][0], acc[i][1], acc[i][2], acc[i][3]);
        *(float4*)(g_xz + (size_t)row * C2 + col0 + tx * 4) = v;
    }
}

// ---------------- kernel 5: depthwise 3x3 conv + bias + SiLU ----------------
__global__ void k_conv(const float* __restrict__ cw, const float* __restrict__ cb) {
    int bp = blockIdx.x;              // b*L + p
    int d = threadIdx.x;              // 192
    int b = bp >> 12, p = bp & (LL - 1);
    int i = p >> 6, j = p & 63;
    float acc = cb[d];
#pragma unroll
    for (int ky = 0; ky < 3; ky++) {
        int y = i + ky - 1;
        if ((unsigned)y < HH) {
#pragma unroll
            for (int kx = 0; kx < 3; kx++) {
                int xx = j + kx - 1;
                if ((unsigned)xx < WW) {
                    acc += g_xz[(size_t)(((b << 12) + (y << 6) + xx)) * C2 + d]
                         * cw[d * 9 + ky * 3 + kx];
                }
            }
        }
    }
    float sv = acc / (1.0f + expf(-acc));
    g_xconv[(size_t)bp * DI + d] = sv;
}

// ---------------- kernel 6: x_dbl projection + delta/u/B/C ----------------
#define LT 32
__global__ void k_xproj(const float* __restrict__ xpw, const float* __restrict__ dtw,
                        const float* __restrict__ dirB, const float* __restrict__ dt_bias) {
    __shared__ float xs[LT][DI + 1];        // pad 193: conflict-free column reads
    __shared__ float xdbl[LT][CDT + 3];     // pad 41: conflict-free writes
    int bk = blockIdx.x;                    // 16
    int b = bk >> 2, k = bk & 3;
    int l0 = blockIdx.y * LT;
    int tid = threadIdx.x;                  // 256

    for (int t = tid; t < LT * DI; t += 256) {
        int li = t / DI, d = t % DI;
        int pos = g_idx[k][l0 + li];
        xs[li][d] = g_xconv[(size_t)((b << 12) + pos) * DI + d];
    }
    __syncthreads();

    for (int t = tid; t < CDT * LT; t += 256) {
        int c = t >> 5, li = t & (LT - 1);
        const float* wrow = xpw + (size_t)(k * CDT + c) * DI;
        float acc = 0.f;
#pragma unroll 8
        for (int d = 0; d < DI; d++) acc += xs[li][d] * __ldg(&wrow[d]);
        xdbl[li][c] = acc;
    }
    __syncthreads();

    float2* du2 = (float2*)g_du4;
    for (int t = tid; t < LT * DI; t += 256) {
        int li = t / DI, d = t % DI;
        const float* wd = dtw + (size_t)(k * DI + d) * DTR;
        float acc = 0.f;
#pragma unroll
        for (int r = 0; r < DTR; r++) acc += xdbl[li][r] * __ldg(&wd[r]);
        // fused: delta = softplus(dt + bias); pack (delta, u) together
        float xsp = acc + __ldg(&dt_bias[k * DI + d]);
        float delta = (xsp > 0.f) ? (xsp + __logf(1.0f + __expf(-xsp)))
                                  : __logf(1.0f + __expf(xsp));
        du2[((size_t)(bk << 12) + l0 + li) * DI + d] = make_float2(delta, xs[li][d]);
    }
    for (int t = tid; t < LT * DS; t += 256) {
        int li = t >> 4, n = t & 15;
        g_Bs[((size_t)(bk << 12) + l0 + li) * DS + n] = xdbl[li][DTR + n] + dirB[k * DS + n];
        g_Cs[((size_t)(bk << 12) + l0 + li) * DS + n] = xdbl[li][DTR + DS + n];
    }
}

// ---------------- kernel 7: selective scan, smem double-buffered pipeline ------
// grid: 192 = 16 (b,k) x 12 chunks of 16 channels; block: 64 threads
// thread t: channel ch = t>>2, state quad q = t&3 (states 4q..4q+3)
#define WIN 16
__global__ void k_scan(const float* __restrict__ A_logs, const float* __restrict__ Ds_) {
    __shared__ float4 s_du[2][WIN][8];   // (delta,u) x2 per float4, 16 channels
    __shared__ float4 s_B[2][WIN][4];
    __shared__ float4 s_C[2][WIN][4];

    int blk = blockIdx.x;               // 192
    int bk = blk / 12, chunk = blk % 12;
    int k = bk & 3;
    int t = threadIdx.x;                // 64
    int ch = t >> 2, q = t & 3;
    int ch0 = chunk * 16;
    int d = ch0 + ch;
    int row = k * DI + d;

    float A[4];
    bool powmode = true;
#pragma unroll
    for (int j = 0; j < 4; j++) {
        int n = 4 * q + j;
        A[j] = -expf(A_logs[(size_t)row * DS + n]);
        if (fabsf(A[j] + (float)(n + 1)) > 1e-3f) powmode = false;
    }
    float Dv = Ds_[row];
    float h0 = 0.f, h1 = 0.f, h2 = 0.f, h3 = 0.f;

    const float4* du4 = g_du4 + (size_t)bk * LL * (DI / 2) + (ch0 >> 1);  // row stride 96 float4
    const float4* Bb = (const float4*)(g_Bs + ((size_t)bk << 12) * DS);   // row stride 4 float4
    const float4* Cb = (const float4*)(g_Cs + ((size_t)bk << 12) * DS);
    float* yout = g_ys + ((size_t)bk << 12) * DI;

    // load-thread coordinates
    int li0 = t >> 3, lc0 = t & 7;           // du piece 0
    int li1 = (t + 64) >> 3, lc1 = t & 7;    // du piece 1 (idx = t+64)
    int lib = t >> 2, lqq = t & 3;           // B/C piece

    // preload window 0 into buffer 0
    {
        float4 r0 = __ldg(du4 + (size_t)li0 * 96 + lc0);
        float4 r1 = __ldg(du4 + (size_t)li1 * 96 + lc1);
        float4 rb = __ldg(&Bb[lib * 4 + lqq]);
        float4 rc = __ldg(&Cb[lib * 4 + lqq]);
        s_du[0][li0][lc0] = r0;
        s_du[0][li1][lc1] = r1;
        s_B[0][lib][lqq] = rb;
        s_C[0][lib][lqq] = rc;
    }
    __syncthreads();

    const int NW = LL / WIN;   // 256
    float4 rdu0, rdu1, rB, rC;
    for (int w = 0; w < NW; w++) {
        int buf = w & 1;
        bool pf = (w + 1 < NW);
        if (pf) {
            int lbase = (w + 1) * WIN;
            rdu0 = __ldg(du4 + (size_t)(lbase + li0) * 96 + lc0);
            rdu1 = __ldg(du4 + (size_t)(lbase + li1) * 96 + lc1);
            rB = __ldg(&Bb[(lbase + lib) * 4 + lqq]);
            rC = __ldg(&Cb[(lbase + lib) * 4 + lqq]);
        }
        int l0 = w * WIN;
        if (powmode) {
#pragma unroll
            for (int i = 0; i < WIN; i++) {
                float2 duv = ((const float2*)&s_du[buf][i][0])[ch];
                float4 Bv = s_B[buf][i][q];
                float4 Cv = s_C[buf][i][q];
                float delta = duv.x, u = duv.y;
                float du_ = delta * u;
                float pw = __expf(-delta);
                float pw2 = pw * pw;
                float pw4 = pw2 * pw2;
                float pw8 = pw4 * pw4;
                float pw12 = pw8 * pw4;
                float base = (q == 0) ? 1.0f : (q == 1) ? pw4 : (q == 2) ? pw8 : pw12;
                float e0 = base * pw;
                float e1 = base * pw2;
                float e2 = e1 * pw;
                float e3 = base * pw4;
                h0 = fmaf(du_, Bv.x, h0 * e0);
                h1 = fmaf(du_, Bv.y, h1 * e1);
                h2 = fmaf(du_, Bv.z, h2 * e2);
                h3 = fmaf(du_, Bv.w, h3 * e3);
                float y = fmaf(h0, Cv.x, h1 * Cv.y) + fmaf(h2, Cv.z, h3 * Cv.w);
                y += __shfl_xor_sync(0xFFFFFFFFu, y, 1);
                y += __shfl_xor_sync(0xFFFFFFFFu, y, 2);
                if (q == 0) yout[(size_t)(l0 + i) * DI + d] = y + Dv * u;
            }
        } else {
#pragma unroll
            for (int i = 0; i < WIN; i++) {
                float2 duv = ((const float2*)&s_du[buf][i][0])[ch];
                float4 Bv = s_B[buf][i][q];
                float4 Cv = s_C[buf][i][q];
                float delta = duv.x, u = duv.y;
                float du_ = delta * u;
                float e0 = __expf(delta * A[0]);
                float e1 = __expf(delta * A[1]);
                float e2 = __expf(delta * A[2]);
                float e3 = __expf(delta * A[3]);
                h0 = fmaf(du_, Bv.x, h0 * e0);
                h1 = fmaf(du_, Bv.y, h1 * e1);
                h2 = fmaf(du_, Bv.z, h2 * e2);
                h3 = fmaf(du_, Bv.w, h3 * e3);
                float y = fmaf(h0, Cv.x, h1 * Cv.y) + fmaf(h2, Cv.z, h3 * Cv.w);
                y += __shfl_xor_sync(0xFFFFFFFFu, y, 1);
                y += __shfl_xor_sync(0xFFFFFFFFu, y, 2);
                if (q == 0) yout[(size_t)(l0 + i) * DI + d] = y + Dv * u;
            }
        }
        if (pf) {
            int nbuf = buf ^ 1;
            s_du[nbuf][li0][lc0] = rdu0;
            s_du[nbuf][li1][lc1] = rdu1;
            s_B[nbuf][lib][lqq] = rB;
            s_C[nbuf][lib][lqq] = rC;
        }
        __syncthreads();
    }
}

// ---------------- kernel 8: direction fusion + LN + SiLU gate + out-proj ------
__global__ void k_final(const float* __restrict__ ln_g, const float* __restrict__ ln_b,
                        const float* __restrict__ opw, float* __restrict__ out) {
    __shared__ float tbuf[DI];
    __shared__ float w1s[6], w2s[6];
    __shared__ float mrs[2];
    int bp = blockIdx.x;               // b*L + p
    int b = bp >> 12, p = bp & (LL - 1);
    int d = threadIdx.x;               // 192

    float acc = 0.f;
#pragma unroll
    for (int k = 0; k < KK; k++) {
        int l = g_inv[k][p];
        acc += g_ys[((size_t)(((b << 2) + k) << 12) + l) * DI + d] * g_wpf[p][k];
    }

    // block reduce: sum, sumsq
    float s1 = acc, s2 = acc * acc;
#pragma unroll
    for (int o = 16; o; o >>= 1) {
        s1 += __shfl_xor_sync(0xFFFFFFFFu, s1, o);
        s2 += __shfl_xor_sync(0xFFFFFFFFu, s2, o);
    }
    int wid = d >> 5, lid = d & 31;
    if (lid == 0) { w1s[wid] = s1; w2s[wid] = s2; }
    __syncthreads();
    if (d == 0) {
        float t1 = 0.f, t2 = 0.f;
#pragma unroll
        for (int w = 0; w < 6; w++) { t1 += w1s[w]; t2 += w2s[w]; }
        float mean = t1 * (1.0f / DI);
        float var = t2 * (1.0f / DI) - mean * mean;
        mrs[0] = mean;
        mrs[1] = rsqrtf(var + 1e-5f);
    }
    __syncthreads();

    float yn = (acc - mrs[0]) * mrs[1] * ln_g[d] + ln_b[d];
    float z = g_xz[(size_t)((b << 12) + p) * C2 + DI + d];
    float tv = yn * (z / (1.0f + expf(-z)));
    tbuf[d] = tv;
    __syncthreads();

    if (d < DM) {
        const float* wr = opw + (size_t)d * DI;
        float o = 0.f;
#pragma unroll 8
        for (int dd = 0; dd < DI; dd++) o += tbuf[dd] * __ldg(&wr[dd]);
        out[(size_t)bp * DM + d] = o;
    }
}

// ---------------- launch ----------------
extern "C" void kernel_launch(void* const* d_in, const int* in_sizes, int n_in,
                              void* d_out, int out_size) {
    const float* x          = (const float*)d_in[0];
    const float* in_proj_w  = (const float*)d_in[1];
    const float* conv_w     = (const float*)d_in[2];
    const float* conv_b     = (const float*)d_in[3];
    const float* x_proj_w   = (const float*)d_in[4];
    const float* dt_projs_w = (const float*)d_in[5];
    const float* dt_projs_b = (const float*)d_in[6];
    const float* A_logs     = (const float*)d_in[7];
    const float* Ds         = (const float*)d_in[8];
    const float* dir_Bs     = (const float*)d_in[9];
    const float* pf_w1      = (const float*)d_in[10];
    const float* pf_b1      = (const float*)d_in[11];
    const float* pf_w2      = (const float*)d_in[12];
    const float* pf_b2      = (const float*)d_in[13];
    const float* ln_g       = (const float*)d_in[14];
    const float* ln_b       = (const float*)d_in[15];
    const float* out_proj_w = (const float*)d_in[16];
    float* out = (float*)d_out;

    k_orders<<<LL / 256, 256>>>(pf_w1, pf_b1, pf_w2, pf_b2);
    k_rank<<<dim3(LL / 256, 2), 256>>>();
    k_invperm<<<(KK * LL) / 256, 256>>>();
    k_inproj<<<dim3(C2 / GN, BB * LL / GM), 256>>>(x, in_proj_w);
    k_conv<<<BB * LL, DI>>>(conv_w, conv_b);
    k_xproj<<<dim3(BB * KK, LL / LT), 256>>>(x_proj_w, dt_projs_w, dir_Bs, dt_projs_b);
    k_scan<<<BB * KK * 12, 64>>>(A_logs, Ds);
    k_final<<<BB * LL, DI>>>(ln_g, ln_b, out_proj_w, out);
}